// round 11
// baseline (speedup 1.0000x reference)
#include <cuda_runtime.h>
#include <math.h>

#define NLEVELS 16
#define TSIZE (1u << 19)
#define TMASK (TSIZE - 1u)
#define HIDDEN 64
#define INDIM 32
#define OUTDIM 16
#define P2 2654435761u
#define P3 805459861u
#define TPB 256
#define NWARPS (TPB / 32)
#define NDENSE 6
#define NPMAX (1 << 20)
#define NBUCKETS 4096

// dense segments: levels 0-4 linear (stride=res), level 5 (res=81, hashed in
// reference) duplicated densely with stride 82.
#define DSZ0 4370
#define DSZ1 12721
#define DSZ2 30785
#define DSZ3 81401
#define DSZ4 208921
#define DSZ5 551368
#define DOFF0 0
#define DOFF1 (DOFF0 + DSZ0)
#define DOFF2 (DOFF1 + DSZ1)
#define DOFF3 (DOFF2 + DSZ2)
#define DOFF4 (DOFF3 + DSZ3)
#define DOFF5 (DOFF4 + DSZ4)
#define DTOT  (DOFF5 + DSZ5)

// packed constants: W0 [0,2048) | W1T [2048,3072) | b0 [3072,3136) | b1 [3136,3152)
#define OW1  2048
#define OB0  3072
#define OB1  3136
#define CTOT 3152

__device__ float4 gDense[DTOT];
__device__ __align__(16) float gStage[CTOT];
__device__ float4 gXs[NPMAX];          // sorted (ux,uy,uz, idx-as-float-bits)
__device__ unsigned gHist[NBUCKETS];
__device__ unsigned gOffset[NBUCKETS];

__constant__ __align__(16) float cAll[CTOT];

struct Params {
    float scale[NLEVELS];
};

typedef unsigned long long u64;

__device__ __forceinline__ u64 pk2(float lo, float hi) {
    u64 r;
    asm("mov.b64 %0, {%1, %2};" : "=l"(r) : "f"(lo), "f"(hi));
    return r;
}
__device__ __forceinline__ void upk2(float& lo, float& hi, u64 v) {
    asm("mov.b64 {%0, %1}, %2;" : "=f"(lo), "=f"(hi) : "l"(v));
}
__device__ __forceinline__ u64 fma2(u64 a, u64 b, u64 c) {
    u64 r;
    asm("fma.rn.f32x2 %0, %1, %2, %3;" : "=l"(r) : "l"(a), "l"(b), "l"(c));
    return r;
}
__device__ __forceinline__ u64 mul2(u64 a, u64 b) {
    u64 r;
    asm("mul.rn.f32x2 %0, %1, %2;" : "=l"(r) : "l"(a), "l"(b));
    return r;
}

__device__ __forceinline__ float2 cond_ldg_f2_indep(const float2* addr, unsigned cond) {
    float2 r;
    asm("{\n\t"
        ".reg .pred p;\n\t"
        "setp.ne.u32 p, %2, 0;\n\t"
        "mov.f32 %0, 0f00000000;\n\t"
        "mov.f32 %1, 0f00000000;\n\t"
        "@p ld.global.nc.v2.f32 {%0,%1}, [%3];\n\t"
        "}"
        : "=f"(r.x), "=f"(r.y)
        : "r"(cond), "l"(addr));
    return r;
}

__device__ __forceinline__ unsigned bucket_key(float ux, float uy, float uz) {
    unsigned bx = min(15, (int)(ux * 16.0f));
    unsigned by = min(15, (int)(uy * 16.0f));
    unsigned bz = min(15, (int)(uz * 16.0f));
    return bx | (by << 4) | (bz << 8);
}

// ---- setup: dense dup tables + packed constants staging ----
__global__ void setup_kernel(const float* __restrict__ table,
                             const float* __restrict__ W0,
                             const float* __restrict__ b0,
                             const float* __restrict__ W1,
                             const float* __restrict__ b1)
{
    int t = blockIdx.x * blockDim.x + threadIdx.x;

    if (t < CTOT) {
        float v;
        if (t < OW1) {
            v = W0[t];
        } else if (t < OB0) {
            int u = t - OW1;
            int j = u >> 4, o = u & 15;
            v = W1[o * HIDDEN + j];
        } else if (t < OB1) {
            v = b0[t - OB0];
        } else {
            v = b1[t - OB1];
        }
        gStage[t] = v;
    }

    if (t >= DTOT) return;

    if (t < DOFF5) {
        int l, off;
        if      (t < DOFF1) { l = 0; off = DOFF0; }
        else if (t < DOFF2) { l = 1; off = DOFF1; }
        else if (t < DOFF3) { l = 2; off = DOFF2; }
        else if (t < DOFF4) { l = 3; off = DOFF3; }
        else                { l = 4; off = DOFF4; }
        unsigned j = t - off;
        const float2* tl = (const float2*)table + (size_t)l * TSIZE;
        float2 a = tl[j];
        float2 b = tl[j + 1];
        gDense[t] = make_float4(a.x, a.y, b.x, b.y);
    } else {
        unsigned j = t - DOFF5;
        unsigned cz = j / 6724u;
        unsigned rem = j - cz * 6724u;
        unsigned cy = rem / 82u;
        unsigned cx = rem - cy * 82u;
        unsigned H = cy * P2 ^ cz * P3;
        const float2* tl = (const float2*)table + (size_t)5 * TSIZE;
        float2 a = tl[(cx ^ H) & TMASK];
        float2 b = tl[((cx + 1u) ^ H) & TMASK];
        gDense[t] = make_float4(a.x, a.y, b.x, b.y);
    }
}

// ---- binning pass 1: histogram ----
__global__ void hist_kernel(const float* __restrict__ x, int N) {
    int i = blockIdx.x * blockDim.x + threadIdx.x;
    if (i >= N) return;
    float ux = fminf(fmaxf((x[3 * i + 0] + 1.0f) * 0.5f, 0.0f), 1.0f);
    float uy = fminf(fmaxf((x[3 * i + 1] + 1.0f) * 0.5f, 0.0f), 1.0f);
    float uz = fminf(fmaxf((x[3 * i + 2] + 1.0f) * 0.5f, 0.0f), 1.0f);
    atomicAdd(&gHist[bucket_key(ux, uy, uz)], 1u);
}

// ---- binning pass 2: exclusive scan (single block, 1024 threads, 4/thread) ----
__global__ void scan_kernel() {
    __shared__ unsigned s[1024];
    int t = threadIdx.x;
    unsigned v0 = gHist[4 * t + 0];
    unsigned v1 = gHist[4 * t + 1];
    unsigned v2 = gHist[4 * t + 2];
    unsigned v3 = gHist[4 * t + 3];
    s[t] = v0 + v1 + v2 + v3;
    __syncthreads();
    for (int d = 1; d < 1024; d <<= 1) {
        unsigned add = (t >= d) ? s[t - d] : 0u;
        __syncthreads();
        s[t] += add;
        __syncthreads();
    }
    unsigned excl = (t == 0) ? 0u : s[t - 1];
    gOffset[4 * t + 0] = excl;
    gOffset[4 * t + 1] = excl + v0;
    gOffset[4 * t + 2] = excl + v0 + v1;
    gOffset[4 * t + 3] = excl + v0 + v1 + v2;
}

// ---- binning pass 3: scatter (ux,uy,uz,idx) into sorted order ----
__global__ void scatter_kernel(const float* __restrict__ x, int N) {
    int i = blockIdx.x * blockDim.x + threadIdx.x;
    if (i >= N) return;
    float ux = fminf(fmaxf((x[3 * i + 0] + 1.0f) * 0.5f, 0.0f), 1.0f);
    float uy = fminf(fmaxf((x[3 * i + 1] + 1.0f) * 0.5f, 0.0f), 1.0f);
    float uz = fminf(fmaxf((x[3 * i + 2] + 1.0f) * 0.5f, 0.0f), 1.0f);
    unsigned pos = atomicAdd(&gOffset[bucket_key(ux, uy, uz)], 1u);
    gXs[pos] = make_float4(ux, uy, uz, __int_as_float(i));
}

__global__ __launch_bounds__(TPB, 4) void sdf_fused_kernel(
    const float* __restrict__ table,
    float* __restrict__ out,
    int N, Params p)
{
    __shared__ float sOut[TPB * 16];
    __shared__ int sIdx[TPB];

    int tid = threadIdx.x;
    int iBase = blockIdx.x * TPB;
    int i = iBase + tid;
    bool valid = (i < N);
    int ii = valid ? i : 0;

    float4 q = gXs[ii];
    float ux = q.x, uy = q.y, uz = q.z;
    sIdx[tid] = __float_as_int(q.w);

    u64 enc2[NLEVELS];
    const float2* __restrict__ tab = (const float2*)table;

    const unsigned kSTR[NDENSE] = {16u, 23u, 31u, 43u, 59u, 82u};
    const unsigned kOFF[NDENSE] = {DOFF0, DOFF1, DOFF2, DOFF3, DOFF4, DOFF5};

#pragma unroll
    for (int l = 0; l < NLEVELS; l++) {
        float s = p.scale[l];
        float px = fmaf(ux, s, 0.5f);
        float py = fmaf(uy, s, 0.5f);
        float pz = fmaf(uz, s, 0.5f);
        float gx = floorf(px), gy = floorf(py), gz = floorf(pz);
        float fx = px - gx, fy = py - gy, fz = pz - gz;
        unsigned cx = (unsigned)gx, cy = (unsigned)gy, cz = (unsigned)gz;

        float wx0 = 1.0f - fx;
        float wy0 = 1.0f - fy, wz0 = 1.0f - fz;
        u64 fx2 = pk2(fx, fx);
        u64 wx02 = pk2(wx0, wx0);
        u64 acc = pk2(0.0f, 0.0f);

        float wyzA[4];
        wyzA[0] = wy0 * wz0;
        wyzA[1] = fy  * wz0;
        wyzA[2] = wy0 * fz;
        wyzA[3] = fy  * fz;

        if (l < NDENSE) {
            unsigned r = kSTR[l], r2 = r * r;
            unsigned b00 = kOFF[l] + cx + cy * r + cz * r2;
            unsigned bA[4] = {b00, b00 + r, b00 + r2, b00 + r + r2};
            float4 v[4];
#pragma unroll
            for (int c = 0; c < 4; c++) v[c] = __ldg(&gDense[bA[c]]);
#pragma unroll
            for (int c = 0; c < 4; c++) {
                u64 t = mul2(pk2(v[c].x, v[c].y), wx02);
                t = fma2(pk2(v[c].z, v[c].w), fx2, t);
                acc = fma2(t, pk2(wyzA[c], wyzA[c]), acc);
            }
        } else {
            const float2* __restrict__ tl = tab + (size_t)l * TSIZE;
            const float4* __restrict__ tl4 = (const float4*)tl;
            unsigned ty0 = cy * P2, ty1 = ty0 + P2;
            unsigned tz0 = cz * P3, tz1 = tz0 + P3;
            unsigned mask = cx ^ (cx + 1u);
            unsigned np = cx & 1u;

            float4 v[4];
            float2 t2[4];
            unsigned jloA[4];
#pragma unroll
            for (int c = 0; c < 4; c++) {
                unsigned H = ((c & 1u) ? ty1 : ty0) ^ ((c & 2u) ? tz1 : tz0);
                unsigned jlo = (cx ^ H) & TMASK;
                unsigned jhi = (jlo ^ mask) & TMASK;
                jloA[c] = jlo;
                v[c] = __ldg(tl4 + (jlo >> 1));
                t2[c] = cond_ldg_f2_indep(tl + jhi, np);
            }
#pragma unroll
            for (int c = 0; c < 4; c++) {
                unsigned odd = jloA[c] & 1u;
                float2 flo = odd ? make_float2(v[c].z, v[c].w) : make_float2(v[c].x, v[c].y);
                float2 oth = odd ? make_float2(v[c].x, v[c].y) : make_float2(v[c].z, v[c].w);
                float2 fhi = np ? t2[c] : oth;
                u64 t = mul2(pk2(flo.x, flo.y), wx02);
                t = fma2(pk2(fhi.x, fhi.y), fx2, t);
                acc = fma2(t, pk2(wyzA[c], wyzA[c]), acc);
            }
        }
        enc2[l] = acc;
    }

    // ---- MLP with packed f32x2 FMA; weights from constant ----
    const u64* __restrict__ w0q = (const u64*)cAll;
    const u64* __restrict__ w1q = (const u64*)(cAll + OW1);
    const float* __restrict__ cb0 = cAll + OB0;
    const float* __restrict__ cb1 = cAll + OB1;

    u64 acc2[OUTDIM / 2];
#pragma unroll
    for (int o2 = 0; o2 < OUTDIM / 2; o2++)
        acc2[o2] = pk2(cb1[2 * o2], cb1[2 * o2 + 1]);

#pragma unroll 8
    for (int j = 0; j < HIDDEN; j++) {
        u64 h2 = pk2(cb0[j], 0.0f);
#pragma unroll
        for (int k2 = 0; k2 < NLEVELS; k2++)
            h2 = fma2(enc2[k2], w0q[j * NLEVELS + k2], h2);
        float hlo, hhi;
        upk2(hlo, hhi, h2);
        float h = hlo + hhi;

        float z = 100.0f * h;
        float sp = __logf(1.0f + __expf(z)) * 0.01f;
        float a = (z > 20.0f) ? h : sp;

        u64 a2 = pk2(a, a);
#pragma unroll
        for (int o2 = 0; o2 < OUTDIM / 2; o2++)
            acc2[o2] = fma2(a2, w1q[j * (OUTDIM / 2) + o2], acc2[o2]);
    }

    // stage all 16 outputs (sdf + 15 geo) into smem as 4 STS.128
    float4* srow = (float4*)&sOut[tid * 16];
#pragma unroll
    for (int o2 = 0; o2 < 4; o2++) {
        float a0, a1, b0v, b1v;
        upk2(a0, a1, acc2[2 * o2]);
        upk2(b0v, b1v, acc2[2 * o2 + 1]);
        srow[o2] = make_float4(a0, a1, b0v, b1v);
    }
    __syncthreads();

    // ---- scattered output writer: warp-cooperative rows ----
    // out layout: [sdf(N)] then [geo(N,15)]
    float* __restrict__ geo = out + N;
    int lane = tid & 31;
    int wid = tid >> 5;
    for (int r = wid; r < TPB; r += NWARPS) {
        if (iBase + r >= N) break;
        int oi = sIdx[r];
        if (lane < 16) {
            float v = sOut[r * 16 + lane];
            float* addr = (lane == 0) ? (out + oi)
                                      : (geo + (size_t)oi * 15 + (lane - 1));
            *addr = v;
        }
    }
}

extern "C" void kernel_launch(void* const* d_in, const int* in_sizes, int n_in,
                              void* d_out, int out_size)
{
    const float* x     = (const float*)d_in[0];
    const float* table = (const float*)d_in[1];
    const float* W0    = (const float*)d_in[2];
    const float* b0    = (const float*)d_in[3];
    const float* W1    = (const float*)d_in[4];
    const float* b1    = (const float*)d_in[5];
    float* out = (float*)d_out;

    int N = in_sizes[0] / 3;
    if (N > NPMAX) N = NPMAX;

    // setup: dense tables + constants
    setup_kernel<<<(DTOT + 255) / 256, 256>>>(table, W0, b0, W1, b1);
    void* stage = nullptr;
    cudaGetSymbolAddress(&stage, gStage);
    cudaMemcpyToSymbolAsync(cAll, stage, CTOT * sizeof(float), 0,
                            cudaMemcpyDeviceToDevice, 0);

    // binning: histogram -> scan -> scatter
    void* histPtr = nullptr;
    cudaGetSymbolAddress(&histPtr, gHist);
    cudaMemsetAsync(histPtr, 0, NBUCKETS * sizeof(unsigned), 0);
    hist_kernel<<<(N + 255) / 256, 256>>>(x, N);
    scan_kernel<<<1, 1024>>>();
    scatter_kernel<<<(N + 255) / 256, 256>>>(x, N);

    Params p;
    const double pls = exp2(7.0 / 15.0);
    for (int l = 0; l < NLEVELS; l++) {
        double sc = 16.0 * pow(pls, (double)l) - 1.0;
        p.scale[l] = (float)sc;
    }

    int blocks = (N + TPB - 1) / TPB;
    sdf_fused_kernel<<<blocks, TPB>>>(table, out, N, p);
}

// round 12
// speedup vs baseline: 1.0341x; 1.0341x over previous
#include <cuda_runtime.h>
#include <math.h>

#define NLEVELS 16
#define TSIZE (1u << 19)
#define TMASK (TSIZE - 1u)
#define HIDDEN 64
#define INDIM 32
#define OUTDIM 16
#define P2 2654435761u
#define P3 805459861u
#define TPB 256
#define NWARPS (TPB / 32)
#define NDENSE 6
#define NPMAX (1 << 20)
#define NBUCKETS 32768   /* 32^3 */

#define DSZ0 4370
#define DSZ1 12721
#define DSZ2 30785
#define DSZ3 81401
#define DSZ4 208921
#define DSZ5 551368
#define DOFF0 0
#define DOFF1 (DOFF0 + DSZ0)
#define DOFF2 (DOFF1 + DSZ1)
#define DOFF3 (DOFF2 + DSZ2)
#define DOFF4 (DOFF3 + DSZ3)
#define DOFF5 (DOFF4 + DSZ4)
#define DTOT  (DOFF5 + DSZ5)

#define OW1  2048
#define OB0  3072
#define OB1  3136
#define CTOT 3152

__device__ float4 gDense[DTOT];
__device__ __align__(16) float gStage[CTOT];
__device__ float4 gXs[NPMAX];
__device__ unsigned gHist[NBUCKETS];
__device__ unsigned gOffset[NBUCKETS];

__constant__ __align__(16) float cAll[CTOT];

struct Params {
    float scale[NLEVELS];
};

typedef unsigned long long u64;

__device__ __forceinline__ u64 pk2(float lo, float hi) {
    u64 r;
    asm("mov.b64 %0, {%1, %2};" : "=l"(r) : "f"(lo), "f"(hi));
    return r;
}
__device__ __forceinline__ void upk2(float& lo, float& hi, u64 v) {
    asm("mov.b64 {%0, %1}, %2;" : "=f"(lo), "=f"(hi) : "l"(v));
}
__device__ __forceinline__ u64 fma2(u64 a, u64 b, u64 c) {
    u64 r;
    asm("fma.rn.f32x2 %0, %1, %2, %3;" : "=l"(r) : "l"(a), "l"(b), "l"(c));
    return r;
}
__device__ __forceinline__ u64 mul2(u64 a, u64 b) {
    u64 r;
    asm("mul.rn.f32x2 %0, %1, %2;" : "=l"(r) : "l"(a), "l"(b));
    return r;
}

__device__ __forceinline__ float2 cond_ldg_f2_indep(const float2* addr, unsigned cond) {
    float2 r;
    asm("{\n\t"
        ".reg .pred p;\n\t"
        "setp.ne.u32 p, %2, 0;\n\t"
        "mov.f32 %0, 0f00000000;\n\t"
        "mov.f32 %1, 0f00000000;\n\t"
        "@p ld.global.nc.v2.f32 {%0,%1}, [%3];\n\t"
        "}"
        : "=f"(r.x), "=f"(r.y)
        : "r"(cond), "l"(addr));
    return r;
}

__device__ __forceinline__ unsigned bucket_key(float ux, float uy, float uz) {
    unsigned bx = min(31, (int)(ux * 32.0f));
    unsigned by = min(31, (int)(uy * 32.0f));
    unsigned bz = min(31, (int)(uz * 32.0f));
    return bx | (by << 5) | (bz << 10);
}

// ---- setup: dense dup tables + packed constants staging ----
__global__ void setup_kernel(const float* __restrict__ table,
                             const float* __restrict__ W0,
                             const float* __restrict__ b0,
                             const float* __restrict__ W1,
                             const float* __restrict__ b1)
{
    int t = blockIdx.x * blockDim.x + threadIdx.x;

    if (t < CTOT) {
        float v;
        if (t < OW1) {
            v = W0[t];
        } else if (t < OB0) {
            int u = t - OW1;
            int j = u >> 4, o = u & 15;
            v = W1[o * HIDDEN + j];
        } else if (t < OB1) {
            v = b0[t - OB0];
        } else {
            v = b1[t - OB1];
        }
        gStage[t] = v;
    }

    if (t >= DTOT) return;

    if (t < DOFF5) {
        int l, off;
        if      (t < DOFF1) { l = 0; off = DOFF0; }
        else if (t < DOFF2) { l = 1; off = DOFF1; }
        else if (t < DOFF3) { l = 2; off = DOFF2; }
        else if (t < DOFF4) { l = 3; off = DOFF3; }
        else                { l = 4; off = DOFF4; }
        unsigned j = t - off;
        const float2* tl = (const float2*)table + (size_t)l * TSIZE;
        float2 a = tl[j];
        float2 b = tl[j + 1];
        gDense[t] = make_float4(a.x, a.y, b.x, b.y);
    } else {
        unsigned j = t - DOFF5;
        unsigned cz = j / 6724u;
        unsigned rem = j - cz * 6724u;
        unsigned cy = rem / 82u;
        unsigned cx = rem - cy * 82u;
        unsigned H = cy * P2 ^ cz * P3;
        const float2* tl = (const float2*)table + (size_t)5 * TSIZE;
        float2 a = tl[(cx ^ H) & TMASK];
        float2 b = tl[((cx + 1u) ^ H) & TMASK];
        gDense[t] = make_float4(a.x, a.y, b.x, b.y);
    }
}

// ---- binning pass 1: histogram, 4 independent points per thread ----
__global__ void hist_kernel(const float* __restrict__ x, int N, int S) {
    int i = blockIdx.x * blockDim.x + threadIdx.x;
#pragma unroll
    for (int k = 0; k < 4; k++) {
        int j = i + k * S;
        if (j < N) {
            float ux = fminf(fmaxf((x[3 * j + 0] + 1.0f) * 0.5f, 0.0f), 1.0f);
            float uy = fminf(fmaxf((x[3 * j + 1] + 1.0f) * 0.5f, 0.0f), 1.0f);
            float uz = fminf(fmaxf((x[3 * j + 2] + 1.0f) * 0.5f, 0.0f), 1.0f);
            atomicAdd(&gHist[bucket_key(ux, uy, uz)], 1u);
        }
    }
}

// ---- binning pass 2: exclusive scan of 32768 (1024 thr x 32) ----
__global__ void scan_kernel() {
    __shared__ unsigned s[1024];
    int t = threadIdx.x;
    unsigned v[32];
    unsigned sum = 0;
#pragma unroll
    for (int k = 0; k < 32; k++) { v[k] = gHist[t * 32 + k]; sum += v[k]; }
    s[t] = sum;
    __syncthreads();
    for (int d = 1; d < 1024; d <<= 1) {
        unsigned a = (t >= d) ? s[t - d] : 0u;
        __syncthreads();
        s[t] += a;
        __syncthreads();
    }
    unsigned excl = (t == 0) ? 0u : s[t - 1];
#pragma unroll
    for (int k = 0; k < 32; k++) { gOffset[t * 32 + k] = excl; excl += v[k]; }
}

// ---- binning pass 3: scatter, 4 independent chains per thread ----
__global__ void scatter_kernel(const float* __restrict__ x, int N, int S) {
    int i = blockIdx.x * blockDim.x + threadIdx.x;
    float u[4][3];
    unsigned key[4];
#pragma unroll
    for (int k = 0; k < 4; k++) {
        int j = i + k * S;
        if (j < N) {
            u[k][0] = fminf(fmaxf((x[3 * j + 0] + 1.0f) * 0.5f, 0.0f), 1.0f);
            u[k][1] = fminf(fmaxf((x[3 * j + 1] + 1.0f) * 0.5f, 0.0f), 1.0f);
            u[k][2] = fminf(fmaxf((x[3 * j + 2] + 1.0f) * 0.5f, 0.0f), 1.0f);
            key[k] = bucket_key(u[k][0], u[k][1], u[k][2]);
        }
    }
    unsigned pos[4];
#pragma unroll
    for (int k = 0; k < 4; k++)
        if (i + k * S < N) pos[k] = atomicAdd(&gOffset[key[k]], 1u);
#pragma unroll
    for (int k = 0; k < 4; k++) {
        int j = i + k * S;
        if (j < N)
            gXs[pos[k]] = make_float4(u[k][0], u[k][1], u[k][2], __int_as_float(j));
    }
}

__global__ __launch_bounds__(TPB, 4) void sdf_fused_kernel(
    const float* __restrict__ table,
    float* __restrict__ out,
    int N, Params p)
{
    __shared__ float sOut[TPB * 16];
    __shared__ int sIdx[TPB];

    int tid = threadIdx.x;
    int iBase = blockIdx.x * TPB;
    int i = iBase + tid;
    bool valid = (i < N);
    int ii = valid ? i : 0;

    float4 q = gXs[ii];
    float ux = q.x, uy = q.y, uz = q.z;
    sIdx[tid] = __float_as_int(q.w);

    u64 enc2[NLEVELS];
    const float2* __restrict__ tab = (const float2*)table;

    const unsigned kSTR[NDENSE] = {16u, 23u, 31u, 43u, 59u, 82u};
    const unsigned kOFF[NDENSE] = {DOFF0, DOFF1, DOFF2, DOFF3, DOFF4, DOFF5};

#pragma unroll
    for (int l = 0; l < NLEVELS; l++) {
        float s = p.scale[l];
        float px = fmaf(ux, s, 0.5f);
        float py = fmaf(uy, s, 0.5f);
        float pz = fmaf(uz, s, 0.5f);
        float gx = floorf(px), gy = floorf(py), gz = floorf(pz);
        float fx = px - gx, fy = py - gy, fz = pz - gz;
        unsigned cx = (unsigned)gx, cy = (unsigned)gy, cz = (unsigned)gz;

        float wx0 = 1.0f - fx;
        float wy0 = 1.0f - fy, wz0 = 1.0f - fz;
        u64 fx2 = pk2(fx, fx);
        u64 wx02 = pk2(wx0, wx0);
        u64 acc = pk2(0.0f, 0.0f);

        float wyzA[4];
        wyzA[0] = wy0 * wz0;
        wyzA[1] = fy  * wz0;
        wyzA[2] = wy0 * fz;
        wyzA[3] = fy  * fz;

        if (l < NDENSE) {
            unsigned r = kSTR[l], r2 = r * r;
            unsigned b00 = kOFF[l] + cx + cy * r + cz * r2;
            unsigned bA[4] = {b00, b00 + r, b00 + r2, b00 + r + r2};
            float4 v[4];
#pragma unroll
            for (int c = 0; c < 4; c++) v[c] = __ldg(&gDense[bA[c]]);
#pragma unroll
            for (int c = 0; c < 4; c++) {
                u64 t = mul2(pk2(v[c].x, v[c].y), wx02);
                t = fma2(pk2(v[c].z, v[c].w), fx2, t);
                acc = fma2(t, pk2(wyzA[c], wyzA[c]), acc);
            }
        } else {
            const float2* __restrict__ tl = tab + (size_t)l * TSIZE;
            const float4* __restrict__ tl4 = (const float4*)tl;
            unsigned ty0 = cy * P2, ty1 = ty0 + P2;
            unsigned tz0 = cz * P3, tz1 = tz0 + P3;
            unsigned mask = cx ^ (cx + 1u);
            unsigned np = cx & 1u;

            float4 v[4];
            float2 t2[4];
            unsigned jloA[4];
#pragma unroll
            for (int c = 0; c < 4; c++) {
                unsigned H = ((c & 1u) ? ty1 : ty0) ^ ((c & 2u) ? tz1 : tz0);
                unsigned jlo = (cx ^ H) & TMASK;
                unsigned jhi = (jlo ^ mask) & TMASK;
                jloA[c] = jlo;
                v[c] = __ldg(tl4 + (jlo >> 1));
                t2[c] = cond_ldg_f2_indep(tl + jhi, np);
            }
#pragma unroll
            for (int c = 0; c < 4; c++) {
                unsigned odd = jloA[c] & 1u;
                float2 flo = odd ? make_float2(v[c].z, v[c].w) : make_float2(v[c].x, v[c].y);
                float2 oth = odd ? make_float2(v[c].x, v[c].y) : make_float2(v[c].z, v[c].w);
                float2 fhi = np ? t2[c] : oth;
                u64 t = mul2(pk2(flo.x, flo.y), wx02);
                t = fma2(pk2(fhi.x, fhi.y), fx2, t);
                acc = fma2(t, pk2(wyzA[c], wyzA[c]), acc);
            }
        }
        enc2[l] = acc;
    }

    const u64* __restrict__ w0q = (const u64*)cAll;
    const u64* __restrict__ w1q = (const u64*)(cAll + OW1);
    const float* __restrict__ cb0 = cAll + OB0;
    const float* __restrict__ cb1 = cAll + OB1;

    u64 acc2[OUTDIM / 2];
#pragma unroll
    for (int o2 = 0; o2 < OUTDIM / 2; o2++)
        acc2[o2] = pk2(cb1[2 * o2], cb1[2 * o2 + 1]);

#pragma unroll 8
    for (int j = 0; j < HIDDEN; j++) {
        u64 h2 = pk2(cb0[j], 0.0f);
#pragma unroll
        for (int k2 = 0; k2 < NLEVELS; k2++)
            h2 = fma2(enc2[k2], w0q[j * NLEVELS + k2], h2);
        float hlo, hhi;
        upk2(hlo, hhi, h2);
        float h = hlo + hhi;

        float z = 100.0f * h;
        float sp = __logf(1.0f + __expf(z)) * 0.01f;
        float a = (z > 20.0f) ? h : sp;

        u64 a2 = pk2(a, a);
#pragma unroll
        for (int o2 = 0; o2 < OUTDIM / 2; o2++)
            acc2[o2] = fma2(a2, w1q[j * (OUTDIM / 2) + o2], acc2[o2]);
    }

    float4* srow = (float4*)&sOut[tid * 16];
#pragma unroll
    for (int o2 = 0; o2 < 4; o2++) {
        float a0, a1, b0v, b1v;
        upk2(a0, a1, acc2[2 * o2]);
        upk2(b0v, b1v, acc2[2 * o2 + 1]);
        srow[o2] = make_float4(a0, a1, b0v, b1v);
    }
    __syncthreads();

    float* __restrict__ geo = out + N;
    int lane = tid & 31;
    int wid = tid >> 5;
    for (int r = wid; r < TPB; r += NWARPS) {
        if (iBase + r >= N) break;
        int oi = sIdx[r];
        if (lane < 16) {
            float v = sOut[r * 16 + lane];
            float* addr = (lane == 0) ? (out + oi)
                                      : (geo + (size_t)oi * 15 + (lane - 1));
            *addr = v;
        }
    }
}

extern "C" void kernel_launch(void* const* d_in, const int* in_sizes, int n_in,
                              void* d_out, int out_size)
{
    const float* x     = (const float*)d_in[0];
    const float* table = (const float*)d_in[1];
    const float* W0    = (const float*)d_in[2];
    const float* b0    = (const float*)d_in[3];
    const float* W1    = (const float*)d_in[4];
    const float* b1    = (const float*)d_in[5];
    float* out = (float*)d_out;

    int N = in_sizes[0] / 3;
    if (N > NPMAX) N = NPMAX;

    setup_kernel<<<(DTOT + 255) / 256, 256>>>(table, W0, b0, W1, b1);
    void* stage = nullptr;
    cudaGetSymbolAddress(&stage, gStage);
    cudaMemcpyToSymbolAsync(cAll, stage, CTOT * sizeof(float), 0,
                            cudaMemcpyDeviceToDevice, 0);

    void* histPtr = nullptr;
    cudaGetSymbolAddress(&histPtr, gHist);
    cudaMemsetAsync(histPtr, 0, NBUCKETS * sizeof(unsigned), 0);

    int S = (N + 3) / 4;
    int bblocks = (S + 255) / 256;
    hist_kernel<<<bblocks, 256>>>(x, N, S);
    scan_kernel<<<1, 1024>>>();
    scatter_kernel<<<bblocks, 256>>>(x, N, S);

    Params p;
    const double pls = exp2(7.0 / 15.0);
    for (int l = 0; l < NLEVELS; l++) {
        double sc = 16.0 * pow(pls, (double)l) - 1.0;
        p.scale[l] = (float)sc;
    }

    int blocks = (N + TPB - 1) / TPB;
    sdf_fused_kernel<<<blocks, TPB>>>(table, out, N, p);
}